// round 1
// baseline (speedup 1.0000x reference)
#include <cuda_runtime.h>
#include <cuda_bf16.h>
#include <float.h>

// Problem constants (fixed shapes per reference)
#define PN 32768   // points
#define PM 8192    // shortcut (query) points
#define PC 256     // feature channels

#define TS 2048    // tile size (points in smem per iteration)
#define QW 16      // warps per block = queries per block
#define BLOCK (QW * 32)

// One warp handles one query point. The block's QW warps share SMEM coord tiles.
// Branchless per-lane top-2, then shuffle-based warp merge, then row gather.
__global__ __launch_bounds__(BLOCK) void closest_pool_kernel(
    const float* __restrict__ src_feats,
    const float* __restrict__ tgt_feats,
    const float* __restrict__ src_coords,
    const float* __restrict__ tgt_coords,
    const float* __restrict__ src_sc,
    const float* __restrict__ tgt_sc,
    float* __restrict__ out)
{
    __shared__ float4 tile[TS];

    const int side = blockIdx.y;                 // 0 = src, 1 = tgt
    const float* __restrict__ feats  = side ? tgt_feats  : src_feats;
    const float* __restrict__ coords = side ? tgt_coords : src_coords;
    const float* __restrict__ qcoords = side ? tgt_sc    : src_sc;
    float* __restrict__ out_side = out + (size_t)side * PM * PC;

    const int warp = threadIdx.x >> 5;
    const int lane = threadIdx.x & 31;
    const int q = blockIdx.x * QW + warp;        // query index, always < PM

    // Query point (broadcast per warp). a2 mirrors reference: (x*x + y*y) + z*z
    const float qx = qcoords[q * 3 + 0];
    const float qy = qcoords[q * 3 + 1];
    const float qz = qcoords[q * 3 + 2];
    const float a2 = (qx * qx + qy * qy) + qz * qz;

    float d1 = FLT_MAX, d2 = FLT_MAX;
    int   i1 = -1,      i2 = -1;

    for (int base = 0; base < PN; base += TS) {
        __syncthreads();
        // Cooperative tile load: pack {x,y,z,b2}; b2 mirrors reference association.
        for (int t = threadIdx.x; t < TS; t += BLOCK) {
            const int n = base + t;
            const float bx = coords[n * 3 + 0];
            const float by = coords[n * 3 + 1];
            const float bz = coords[n * 3 + 2];
            const float b2 = (bx * bx + by * by) + bz * bz;
            tile[t] = make_float4(bx, by, bz, b2);
        }
        __syncthreads();

        // Each lane scans TS/32 points of the tile.
        #pragma unroll 8
        for (int j = lane; j < TS; j += 32) {
            const float4 p = tile[j];
            // dot rounded once per term; d = fmaf(-2,dot,t) == t - (2*dot) with
            // single rounding, identical to reference's  (a2+b2) - 2.0*(a@b.T).
            const float dot = fmaf(p.x, qx, fmaf(p.y, qy, p.z * qz));
            const float t   = a2 + p.w;
            const float d   = fmaf(-2.0f, dot, t);
            const int   n   = base + j;

            // Branchless top-2 update. Strict '<' keeps the earlier (lower)
            // index on exact ties, matching stable top_k (per-lane indices
            // are visited in ascending order).
            const bool lt1 = d < d1;
            const bool lt2 = d < d2;
            d2 = lt1 ? d1 : (lt2 ? d : d2);
            i2 = lt1 ? i1 : (lt2 ? n : i2);
            d1 = lt1 ? d  : d1;
            i1 = lt1 ? n  : i1;
        }
    }

    // Warp merge of (d1,i1,d2,i2), tie-break toward smaller index.
    #pragma unroll
    for (int off = 16; off > 0; off >>= 1) {
        const float b1 = __shfl_xor_sync(0xFFFFFFFFu, d1, off);
        const float b2v = __shfl_xor_sync(0xFFFFFFFFu, d2, off);
        const int   bi1 = __shfl_xor_sync(0xFFFFFFFFu, i1, off);
        const int   bi2 = __shfl_xor_sync(0xFFFFFFFFu, i2, off);

        const bool aFirst = (d1 < b1) || (d1 == b1 && i1 < bi1);
        const float c1  = aFirst ? b1  : d1;   // loser of the firsts
        const int   ci1 = aFirst ? bi1 : i1;
        const float c2  = aFirst ? d2  : b2v;  // winner side's second
        const int   ci2 = aFirst ? i2  : bi2;

        const float n1  = aFirst ? d1  : b1;
        const int   ni1 = aFirst ? i1  : bi1;

        const bool takeC1 = (c1 < c2) || (c1 == c2 && ci1 < ci2);
        d1 = n1;  i1 = ni1;
        d2 = takeC1 ? c1 : c2;
        i2 = takeC1 ? ci1 : ci2;
    }
    const int sel = __shfl_sync(0xFFFFFFFFu, i2, 0);

    // Gather the selected feature row (256 floats = 64 float4), warp-coalesced.
    const float4* __restrict__ srow = reinterpret_cast<const float4*>(feats + (size_t)sel * PC);
    float4* __restrict__ drow = reinterpret_cast<float4*>(out_side + (size_t)q * PC);
    #pragma unroll
    for (int k = lane; k < PC / 4; k += 32) {
        drow[k] = srow[k];
    }
}

extern "C" void kernel_launch(void* const* d_in, const int* in_sizes, int n_in,
                              void* d_out, int out_size)
{
    const float* src        = (const float*)d_in[0];
    const float* tgt        = (const float*)d_in[1];
    const float* src_coords = (const float*)d_in[2];
    const float* tgt_coords = (const float*)d_in[3];
    const float* src_sc     = (const float*)d_in[4];
    const float* tgt_sc     = (const float*)d_in[5];
    float* out = (float*)d_out;

    dim3 grid(PM / QW, 2);
    closest_pool_kernel<<<grid, BLOCK>>>(src, tgt, src_coords, tgt_coords,
                                         src_sc, tgt_sc, out);
}